// round 17
// baseline (speedup 1.0000x reference)
#include <cuda_runtime.h>
#include <cuda_fp16.h>
#include <cstdint>

// LinearNavigator via warp-level HMMA (mma.sync m16n8k16, f16 in / f32 accum).
// R16: R15 + depth-2 cp.async pipeline for layer-1 inputs:
//   cell[0]   -> double-buffered CstD via LDGSTS (lands where epilogue reads)
//   hidden[0] -> Hin float staging (converted to f16 at phase A)
//   inp       -> 1-register prefetch
// out layout: out[B,5], h_stack[2,B,20], c_stack[2,B,20]

#define NB 1048576
#define HDIM 20
#define HBASE ((size_t)5 * NB)
#define CBASE (HBASE + (size_t)2 * NB * HDIM)

__device__ __forceinline__ float tanhap_(float x) {
    float y; asm("tanh.approx.f32 %0, %1;" : "=f"(y) : "f"(x)); return y;
}
__device__ __forceinline__ float sigm_(float x) {
    return fmaf(0.5f, tanhap_(0.5f * x), 0.5f);
}
__device__ __forceinline__ uint32_t s2u_(const void* p) {
    return (uint32_t)__cvta_generic_to_shared(p);
}
#define CPA16(sm, gp) asm volatile("cp.async.ca.shared.global [%0], [%1], 16;" :: "r"(sm), "l"(gp) : "memory")
#define CPA_COMMIT() asm volatile("cp.async.commit_group;" ::: "memory")
#define CPA_WAIT0()  asm volatile("cp.async.wait_group 0;" ::: "memory")

__device__ __forceinline__ void mma16816(float& d0, float& d1, float& d2, float& d3,
                                         uint32_t a0, uint32_t a1, uint32_t a2, uint32_t a3,
                                         uint32_t b0, uint32_t b1) {
    asm volatile(
        "mma.sync.aligned.m16n8k16.row.col.f32.f16.f16.f32 "
        "{%0,%1,%2,%3}, {%4,%5,%6,%7}, {%8,%9}, {%0,%1,%2,%3};"
        : "+f"(d0), "+f"(d1), "+f"(d2), "+f"(d3)
        : "r"(a0), "r"(a1), "r"(a2), "r"(a3), "r"(b0), "r"(b1));
}

__global__ __launch_bounds__(128)
void navi_mma(const float* __restrict__ inp, const float* __restrict__ hidden,
              const float* __restrict__ cell,
              const float* __restrict__ W_ih1, const float* __restrict__ W_hh1,
              const float* __restrict__ b_ih1, const float* __restrict__ b_hh1,
              const float* __restrict__ W_ih2, const float* __restrict__ W_hh2,
              const float* __restrict__ b_ih2, const float* __restrict__ b_hh2,
              const float* __restrict__ W_out, const float* __restrict__ b_out,
              float* __restrict__ out)
{
    __shared__ __align__(16) __half B1s[80][40];
    __shared__ __align__(16) __half B2s[80][56];
    __shared__ float  Wos[20];
    __shared__ float  bos;
    __shared__ __align__(16) __half A1s[4][16][40];
    __shared__ __align__(16) __half A2s[4][16][56];
    __shared__ __align__(16) float  CstD[4][2][16][20];   // double-buffered c state
    __shared__ __align__(16) float  Hin[4][16][20];       // h0 float staging (cp.async)
    __shared__ __align__(16) float  Hst[4][16][20];

    const int t = threadIdx.x;
    const int w = t >> 5;
    const int lane = t & 31;
    const int g = lane >> 2;
    const int tig = lane & 3;
    const bool oddl = (tig & 1);
    const int myrow = oddl ? g + 8 : g;

    const int r0 = lane / 5,        q0 = lane % 5;
    const int r1 = (lane + 32) / 5, q1 = (lane + 32) % 5;
    const int r2 = (lane + 64) / 5, q2 = (lane + 64) % 5;   // valid iff lane < 16
    const bool has2 = (lane < 16);

    // ---------------- one-time weight fill ----------------
    {
        __half2* z1 = (__half2*)&B1s[0][0];
        for (int i = t; i < 80 * 20; i += 128) z1[i] = __floats2half2_rn(0.f, 0.f);
        __half2* z2 = (__half2*)&B2s[0][0];
        for (int i = t; i < 80 * 28; i += 128) z2[i] = __floats2half2_rn(0.f, 0.f);
    }
    __syncthreads();
    for (int i = t; i < 1600; i += 128) {
        int r = i / 20, k = i % 20;
        int n = 4 * (r % 20) + (r / 20);
        B1s[n][2 + k] = __float2half_rn(W_hh1[i]);
        B2s[n][k]      = __float2half_rn(W_ih2[i]);
        B2s[n][20 + k] = __float2half_rn(W_hh2[i]);
    }
    for (int i = t; i < 160; i += 128) {
        int r = i / 2, k = i % 2;
        int n = 4 * (r % 20) + (r / 20);
        B1s[n][k] = __float2half_rn(W_ih1[i]);
    }
    for (int i = t; i < 80; i += 128) {
        int n = 4 * (i % 20) + (i / 20);
        B1s[n][22] = __float2half_rn(b_ih1[i] + b_hh1[i]);
        B2s[n][40] = __float2half_rn(b_ih2[i] + b_hh2[i]);
    }
    if (t < 20) Wos[t] = W_out[t];
    if (t == 20) bos = b_out[0];
    __syncthreads();

    // ---------------- prologue: prefetch tile 0 layer-1 inputs ----------------
    float v_pref = 0.f;
    {
        const size_t b0 = (size_t)blockIdx.x * 512 + (size_t)w * 32;  // itile 0
        if (lane < 16) {
            const size_t e = b0 + lane;
            #pragma unroll
            for (int q = 0; q < 5; ++q) {
                CPA16(s2u_(&CstD[w][0][lane][4*q]), &cell[e * HDIM + 4*q]);
                CPA16(s2u_(&Hin[w][lane][4*q]),     &hidden[e * HDIM + 4*q]);
            }
            v_pref = inp[e];
        }
        CPA_COMMIT();
    }

    int buf = 0;
    // ---------------- tile loop: 8 m-tiles of 16 elements per warp ----------------
    #pragma unroll 1
    for (int itile = 0; itile < 8; ++itile) {
        const int it = itile >> 1, mt = itile & 1;
        const size_t base = ((size_t)blockIdx.x * 4 + it) * 128 + (size_t)w * 32 + mt * 16;

        // ---- wait for prefetched c0/h0 ----
        CPA_WAIT0();
        __syncwarp();

        // ---- phase A: preproc (register v) + convert Hin -> A1s ----
        if (lane < 16) {
            const float v = v_pref;
            const float av = fabsf(v);
            float x0, x1;
            if (av >= 4.5399929762484854e-05f) {
                x0 = __logf(av + 1e-8f) * 0.1f;
                x1 = (v > 0.0f) ? 1.0f : -1.0f;
            } else {
                x0 = -1.0f;
                x1 = 22026.465794806718f * v;
            }
            const float4* Hq = (const float4*)&Hin[w][lane][0];
            float4 h0 = Hq[0], h1 = Hq[1], h2 = Hq[2], h3 = Hq[3], h4 = Hq[4];
            __half2* Ar = (__half2*)&A1s[w][lane][0];
            Ar[0]  = __floats2half2_rn(x0, x1);
            Ar[1]  = __floats2half2_rn(h0.x, h0.y);
            Ar[2]  = __floats2half2_rn(h0.z, h0.w);
            Ar[3]  = __floats2half2_rn(h1.x, h1.y);
            Ar[4]  = __floats2half2_rn(h1.z, h1.w);
            Ar[5]  = __floats2half2_rn(h2.x, h2.y);
            Ar[6]  = __floats2half2_rn(h2.z, h2.w);
            Ar[7]  = __floats2half2_rn(h3.x, h3.y);
            Ar[8]  = __floats2half2_rn(h3.z, h3.w);
            Ar[9]  = __floats2half2_rn(h4.x, h4.y);
            Ar[10] = __floats2half2_rn(h4.z, h4.w);
            Ar[11] = __floats2half2_rn(1.0f, 0.0f);   // bias col 22
            Ar[12] = __floats2half2_rn(0.f, 0.f);
            Ar[13] = __floats2half2_rn(0.f, 0.f);
            Ar[14] = __floats2half2_rn(0.f, 0.f);
            Ar[15] = __floats2half2_rn(0.f, 0.f);
        }
        __syncwarp();

        // ---- issue next-tile layer-1 prefetch (clamped at last tile) ----
        {
            const int ni = (itile < 7) ? itile + 1 : 7;
            const size_t nbase = ((size_t)blockIdx.x * 4 + (ni >> 1)) * 128 + (size_t)w * 32 + (ni & 1) * 16;
            if (lane < 16) {
                const size_t e = nbase + lane;
                #pragma unroll
                for (int q = 0; q < 5; ++q) {
                    CPA16(s2u_(&CstD[w][buf ^ 1][lane][4*q]), &cell[e * HDIM + 4*q]);
                    CPA16(s2u_(&Hin[w][lane][4*q]),           &hidden[e * HDIM + 4*q]);
                }
                v_pref = inp[e];
            }
            CPA_COMMIT();
        }

        // ---- layer-2 state register prefetch (current tile) ----
        const float* c1base = cell   + (size_t)NB * HDIM;
        const float* h1base = hidden + (size_t)NB * HDIM;
        float4 c1a = *(const float4*)&c1base[(base + r0) * HDIM + 4*q0];
        float4 h1a = *(const float4*)&h1base[(base + r0) * HDIM + 4*q0];
        float4 c1b = *(const float4*)&c1base[(base + r1) * HDIM + 4*q1];
        float4 h1b = *(const float4*)&h1base[(base + r1) * HDIM + 4*q1];
        float4 c1c = make_float4(0.f, 0.f, 0.f, 0.f);
        float4 h1c = make_float4(0.f, 0.f, 0.f, 0.f);
        if (has2) {
            c1c = *(const float4*)&c1base[(base + r2) * HDIM + 4*q2];
            h1c = *(const float4*)&h1base[(base + r2) * HDIM + 4*q2];
        }

        float (*Cst)[20] = CstD[w][buf];

        // ---- layer 1: A fragments (K=32, 2 slices) ----
        uint32_t a1f[2][4];
        #pragma unroll
        for (int s = 0; s < 2; ++s) {
            a1f[s][0] = *(const uint32_t*)&A1s[w][g][16*s + 2*tig];
            a1f[s][1] = *(const uint32_t*)&A1s[w][g+8][16*s + 2*tig];
            a1f[s][2] = *(const uint32_t*)&A1s[w][g][16*s + 2*tig + 8];
            a1f[s][3] = *(const uint32_t*)&A1s[w][g+8][16*s + 2*tig + 8];
        }

        #pragma unroll 2
        for (int nt = 0; nt < 10; ++nt) {
            float d0 = 0.f, d1 = 0.f, d2 = 0.f, d3 = 0.f;
            #pragma unroll
            for (int s = 0; s < 2; ++s) {
                uint32_t b0 = *(const uint32_t*)&B1s[8*nt + g][16*s + 2*tig];
                uint32_t b1 = *(const uint32_t*)&B1s[8*nt + g][16*s + 2*tig + 8];
                mma16816(d0, d1, d2, d3, a1f[s][0], a1f[s][1], a1f[s][2], a1f[s][3], b0, b1);
            }
            const int j = 2*nt + (tig >> 1);
            float sh0 = __shfl_xor_sync(0xffffffffu, oddl ? d0 : d2, 1);
            float sh1 = __shfl_xor_sync(0xffffffffu, oddl ? d1 : d3, 1);
            float gi = oddl ? sh0 : d0;
            float gf = oddl ? sh1 : d1;
            float gg = oddl ? d2 : sh0;
            float go = oddl ? d3 : sh1;
            float cold = Cst[myrow][j];
            float cn = sigm_(gf) * cold + sigm_(gi) * tanhap_(gg);
            float hn = sigm_(go) * tanhap_(cn);
            Cst[myrow][j] = cn;
            Hst[w][myrow][j] = hn;
            A2s[w][myrow][j] = __float2half_rn(hn);
        }
        __syncwarp();

        // ---- fused: store h0/c0; refill Cst<-c1, A2s<-h1 ----
        {
            size_t e0 = base + r0, e1 = base + r1;
            *(float4*)&out[HBASE + e0 * HDIM + 4*q0] = *(const float4*)&Hst[w][r0][4*q0];
            *(float4*)&out[CBASE + e0 * HDIM + 4*q0] = *(const float4*)&Cst[r0][4*q0];
            *(float4*)&Cst[r0][4*q0] = c1a;
            *(__half2*)&A2s[w][r0][20 + 4*q0]     = __floats2half2_rn(h1a.x, h1a.y);
            *(__half2*)&A2s[w][r0][20 + 4*q0 + 2] = __floats2half2_rn(h1a.z, h1a.w);
            *(float4*)&out[HBASE + e1 * HDIM + 4*q1] = *(const float4*)&Hst[w][r1][4*q1];
            *(float4*)&out[CBASE + e1 * HDIM + 4*q1] = *(const float4*)&Cst[r1][4*q1];
            *(float4*)&Cst[r1][4*q1] = c1b;
            *(__half2*)&A2s[w][r1][20 + 4*q1]     = __floats2half2_rn(h1b.x, h1b.y);
            *(__half2*)&A2s[w][r1][20 + 4*q1 + 2] = __floats2half2_rn(h1b.z, h1b.w);
            if (has2) {
                size_t e2 = base + r2;
                *(float4*)&out[HBASE + e2 * HDIM + 4*q2] = *(const float4*)&Hst[w][r2][4*q2];
                *(float4*)&out[CBASE + e2 * HDIM + 4*q2] = *(const float4*)&Cst[r2][4*q2];
                *(float4*)&Cst[r2][4*q2] = c1c;
                *(__half2*)&A2s[w][r2][20 + 4*q2]     = __floats2half2_rn(h1c.x, h1c.y);
                *(__half2*)&A2s[w][r2][20 + 4*q2 + 2] = __floats2half2_rn(h1c.z, h1c.w);
                __half2* Ar = (__half2*)&A2s[w][lane][40];
                Ar[0] = __floats2half2_rn(1.0f, 0.0f);   // bias col 40
                Ar[1] = __floats2half2_rn(0.f, 0.f);
                Ar[2] = __floats2half2_rn(0.f, 0.f);
                Ar[3] = __floats2half2_rn(0.f, 0.f);
            }
        }
        __syncwarp();

        // ---- layer 2: A fragments (K=48, 3 slices) ----
        uint32_t a2f[3][4];
        #pragma unroll
        for (int s = 0; s < 3; ++s) {
            a2f[s][0] = *(const uint32_t*)&A2s[w][g][16*s + 2*tig];
            a2f[s][1] = *(const uint32_t*)&A2s[w][g+8][16*s + 2*tig];
            a2f[s][2] = *(const uint32_t*)&A2s[w][g][16*s + 2*tig + 8];
            a2f[s][3] = *(const uint32_t*)&A2s[w][g+8][16*s + 2*tig + 8];
        }

        float o_acc = 0.f;
        #pragma unroll 2
        for (int nt = 0; nt < 10; ++nt) {
            float d0 = 0.f, d1 = 0.f, d2 = 0.f, d3 = 0.f;
            #pragma unroll
            for (int s = 0; s < 3; ++s) {
                uint32_t b0 = *(const uint32_t*)&B2s[8*nt + g][16*s + 2*tig];
                uint32_t b1 = *(const uint32_t*)&B2s[8*nt + g][16*s + 2*tig + 8];
                mma16816(d0, d1, d2, d3, a2f[s][0], a2f[s][1], a2f[s][2], a2f[s][3], b0, b1);
            }
            const int j = 2*nt + (tig >> 1);
            float sh0 = __shfl_xor_sync(0xffffffffu, oddl ? d0 : d2, 1);
            float sh1 = __shfl_xor_sync(0xffffffffu, oddl ? d1 : d3, 1);
            float gi = oddl ? sh0 : d0;
            float gf = oddl ? sh1 : d1;
            float gg = oddl ? d2 : sh0;
            float go = oddl ? d3 : sh1;
            float cold = Cst[myrow][j];
            float cn = sigm_(gf) * cold + sigm_(gi) * tanhap_(gg);
            float hn = sigm_(go) * tanhap_(cn);
            Cst[myrow][j] = cn;
            Hst[w][myrow][j] = hn;
            o_acc += hn * Wos[j];
        }
        __syncwarp();

        // ---- store h_stack[1]/c_stack[1] ----
        {
            size_t e0 = base + r0, e1 = base + r1;
            *(float4*)&out[HBASE + (size_t)NB * HDIM + e0 * HDIM + 4*q0] = *(const float4*)&Hst[w][r0][4*q0];
            *(float4*)&out[CBASE + (size_t)NB * HDIM + e0 * HDIM + 4*q0] = *(const float4*)&Cst[r0][4*q0];
            *(float4*)&out[HBASE + (size_t)NB * HDIM + e1 * HDIM + 4*q1] = *(const float4*)&Hst[w][r1][4*q1];
            *(float4*)&out[CBASE + (size_t)NB * HDIM + e1 * HDIM + 4*q1] = *(const float4*)&Cst[r1][4*q1];
            if (has2) {
                size_t e2 = base + r2;
                *(float4*)&out[HBASE + (size_t)NB * HDIM + e2 * HDIM + 4*q2] = *(const float4*)&Hst[w][r2][4*q2];
                *(float4*)&out[CBASE + (size_t)NB * HDIM + e2 * HDIM + 4*q2] = *(const float4*)&Cst[r2][4*q2];
            }
        }

        // ---- head ----
        float s_o = o_acc + __shfl_xor_sync(0xffffffffu, o_acc, 2);
        if (tig == 0) {
            size_t e = base + g;
            float o = bos + s_o;
            float* o5 = out + e * 5;
            #pragma unroll
            for (int s = 0; s < 5; ++s) o5[s] = o * (float)(s + 1);
        }
        if (tig == 1) {
            size_t e = base + g + 8;
            float o = bos + s_o;
            float* o5 = out + e * 5;
            #pragma unroll
            for (int s = 0; s < 5; ++s) o5[s] = o * (float)(s + 1);
        }
        __syncwarp();
        buf ^= 1;
    }
}

extern "C" void kernel_launch(void* const* d_in, const int* in_sizes, int n_in,
                              void* d_out, int out_size) {
    const float* inp    = (const float*)d_in[0];
    const float* hidden = (const float*)d_in[1];
    const float* cell   = (const float*)d_in[2];
    const float* W_ih1  = (const float*)d_in[3];
    const float* W_hh1  = (const float*)d_in[4];
    const float* b_ih1  = (const float*)d_in[5];
    const float* b_hh1  = (const float*)d_in[6];
    const float* W_ih2  = (const float*)d_in[7];
    const float* W_hh2  = (const float*)d_in[8];
    const float* b_ih2  = (const float*)d_in[9];
    const float* b_hh2  = (const float*)d_in[10];
    const float* W_out  = (const float*)d_in[11];
    const float* b_out  = (const float*)d_in[12];
    float* out = (float*)d_out;

    navi_mma<<<2048, 128>>>(inp, hidden, cell,
                            W_ih1, W_hh1, b_ih1, b_hh1,
                            W_ih2, W_hh2, b_ih2, b_hh2,
                            W_out, b_out, out);
}